// round 1
// baseline (speedup 1.0000x reference)
#include <cuda_runtime.h>
#include <math.h>

// Problem constants (MetaS4: B=1024, H=1024, N=32)
#define BSZ 1024
#define HD  1024
#define NS  32

// Scratch (allocation-free rule: __device__ globals)
__device__ float g_y[BSZ * HD];        // GELU(y + u*D), GEMM A operand
__device__ float g_z[BSZ * 2 * HD];    // z = y @ W^T + b

// ---------------------------------------------------------------------------
// Kernel 1: complex diag state update + readout + skip + exact GELU
// One warp per (b,h); lane = n (N=32).
// ---------------------------------------------------------------------------
__global__ __launch_bounds__(256) void s4_update_kernel(
    const float* __restrict__ u,
    const float* __restrict__ st_re, const float* __restrict__ st_im,
    const float* __restrict__ dA_re, const float* __restrict__ dA_im,
    const float* __restrict__ dB_re, const float* __restrict__ dB_im,
    const float* __restrict__ C_re,  const float* __restrict__ C_im,
    const float* __restrict__ D,
    float* __restrict__ ns_re, float* __restrict__ ns_im,
    float* __restrict__ y_scr)
{
    int w    = blockIdx.x * (blockDim.x >> 5) + (threadIdx.x >> 5); // global warp = b*HD + h
    int lane = threadIdx.x & 31;
    int h    = w & (HD - 1);

    long base = (long)w * NS + lane;   // [B,H,N] flat
    int  ph   = h * NS + lane;         // [H,N] flat

    float sre = st_re[base];
    float sim = st_im[base];
    float are = dA_re[ph], aim = dA_im[ph];
    float bre = dB_re[ph], bim = dB_im[ph];
    float uu  = u[w];

    float nre = fmaf(are, sre, fmaf(-aim, sim, bre * uu));
    float nim = fmaf(are, sim, fmaf( aim, sre, bim * uu));

    ns_re[base] = nre;
    ns_im[base] = nim;

    float p = fmaf(C_re[ph], nre, -C_im[ph] * nim);
    #pragma unroll
    for (int o = 16; o > 0; o >>= 1)
        p += __shfl_xor_sync(0xFFFFFFFFu, p, o);

    if (lane == 0) {
        float y = 2.0f * p + uu * D[h];
        // exact GELU: 0.5*y*(1+erf(y/sqrt(2)))
        float g = 0.5f * y * (1.0f + erff(y * 0.7071067811865476f));
        g_y[w] = g;   // w == b*HD + h
    }
    (void)y_scr;
}

// ---------------------------------------------------------------------------
// Kernel 2: Z[M,N2] = Y[M,K] @ W[N2,K]^T + bias    (M=1024, N2=2048, K=1024)
// 128x128x8 register-tiled fp32 SGEMM, 256 threads, TM=TN=8.
// ---------------------------------------------------------------------------
#define BM 128
#define BN 128
#define BK 8
#define TM 8
#define TN 8

__global__ __launch_bounds__(256) void sgemm_nt_kernel(
    const float* __restrict__ A,     // g_y  [M, K]
    const float* __restrict__ Bm,    // W    [N2, K]
    const float* __restrict__ bias,  // [N2]
    float* __restrict__ Z,           // [M, N2]
    int M, int N2, int K)
{
    __shared__ float As[BK][BM];
    __shared__ float Bs[BK][BN];

    const int t  = threadIdx.x;
    const int m0 = blockIdx.y * BM;
    const int n0 = blockIdx.x * BN;
    const int tx = t & 15;        // 0..15 -> n sub-tile
    const int ty = t >> 4;        // 0..15 -> m sub-tile

    // global-load mapping: 128 rows x 8 k per tile, float4 per thread
    const int lrow = t >> 1;          // 0..127
    const int lcol = (t & 1) * 4;     // 0 or 4

    float acc[TM][TN];
    #pragma unroll
    for (int i = 0; i < TM; i++)
        #pragma unroll
        for (int j = 0; j < TN; j++)
            acc[i][j] = 0.0f;

    const float* aPtr = A  + (long)(m0 + lrow) * K + lcol;
    const float* bPtr = Bm + (long)(n0 + lrow) * K + lcol;

    for (int k0 = 0; k0 < K; k0 += BK) {
        float4 a4 = *(const float4*)(aPtr + k0);
        float4 b4 = *(const float4*)(bPtr + k0);
        __syncthreads();
        As[lcol + 0][lrow] = a4.x;
        As[lcol + 1][lrow] = a4.y;
        As[lcol + 2][lrow] = a4.z;
        As[lcol + 3][lrow] = a4.w;
        Bs[lcol + 0][lrow] = b4.x;
        Bs[lcol + 1][lrow] = b4.y;
        Bs[lcol + 2][lrow] = b4.z;
        Bs[lcol + 3][lrow] = b4.w;
        __syncthreads();

        #pragma unroll
        for (int kk = 0; kk < BK; kk++) {
            float ar[TM], br[TN];
            #pragma unroll
            for (int i = 0; i < TM; i++) ar[i] = As[kk][ty * TM + i];
            #pragma unroll
            for (int j = 0; j < TN; j++) br[j] = Bs[kk][tx * TN + j];
            #pragma unroll
            for (int i = 0; i < TM; i++)
                #pragma unroll
                for (int j = 0; j < TN; j++)
                    acc[i][j] = fmaf(ar[i], br[j], acc[i][j]);
        }
    }

    #pragma unroll
    for (int i = 0; i < TM; i++) {
        int m = m0 + ty * TM + i;
        #pragma unroll
        for (int j = 0; j < TN; j += 4) {
            int n = n0 + tx * TN + j;
            float4 v;
            v.x = acc[i][j + 0] + bias[n + 0];
            v.y = acc[i][j + 1] + bias[n + 1];
            v.z = acc[i][j + 2] + bias[n + 2];
            v.w = acc[i][j + 3] + bias[n + 3];
            *(float4*)&Z[(long)m * N2 + n] = v;
        }
    }
}

// ---------------------------------------------------------------------------
// Kernel 3: GLU  y_out[b,j] = z[b,j] * sigmoid(z[b,H+j])
// ---------------------------------------------------------------------------
__global__ __launch_bounds__(256) void glu_kernel(
    const float* __restrict__ Z, float* __restrict__ out)
{
    int i = blockIdx.x * blockDim.x + threadIdx.x;   // 0 .. B*H-1
    int b = i >> 10;           // / HD
    int j = i & (HD - 1);
    float z1 = Z[b * (2 * HD) + j];
    float z2 = Z[b * (2 * HD) + HD + j];
    out[i] = z1 * (1.0f / (1.0f + __expf(-z2)));
}

// ---------------------------------------------------------------------------
// launch
// ---------------------------------------------------------------------------
extern "C" void kernel_launch(void* const* d_in, const int* in_sizes, int n_in,
                              void* d_out, int out_size)
{
    const float* u     = (const float*)d_in[0];
    const float* st_re = (const float*)d_in[1];
    const float* st_im = (const float*)d_in[2];
    const float* dA_re = (const float*)d_in[3];
    const float* dA_im = (const float*)d_in[4];
    const float* dB_re = (const float*)d_in[5];
    const float* dB_im = (const float*)d_in[6];
    const float* C_re  = (const float*)d_in[7];
    const float* C_im  = (const float*)d_in[8];
    const float* D     = (const float*)d_in[9];
    const float* W     = (const float*)d_in[10];
    const float* bias  = (const float*)d_in[11];

    float* out   = (float*)d_out;
    float* y_out = out;                                   // [B, H]
    float* ns_re = out + (long)BSZ * HD;                  // [B, H, N]
    float* ns_im = out + (long)BSZ * HD + (long)BSZ * HD * NS;

    float* ybuf;  cudaGetSymbolAddress((void**)&ybuf, g_y);
    float* zbuf;  cudaGetSymbolAddress((void**)&zbuf, g_z);

    // Kernel 1: one warp per (b,h) -> B*H/8 blocks of 256 threads
    {
        dim3 grid(BSZ * HD / 8);
        s4_update_kernel<<<grid, 256>>>(u, st_re, st_im, dA_re, dA_im,
                                        dB_re, dB_im, C_re, C_im, D,
                                        ns_re, ns_im, ybuf);
    }

    // Kernel 2: SGEMM 1024 x 2048 x 1024
    {
        dim3 grid(2 * HD / BN, BSZ / BM);   // (16, 8)
        sgemm_nt_kernel<<<grid, 256>>>(ybuf, W, bias, zbuf, BSZ, 2 * HD, HD);
    }

    // Kernel 3: GLU
    {
        dim3 grid(BSZ * HD / 256);
        glu_kernel<<<grid, 256>>>(zbuf, y_out);
    }

    (void)in_sizes; (void)n_in; (void)out_size;
}

// round 5
// speedup vs baseline: 2.1811x; 2.1811x over previous
#include <cuda_runtime.h>
#include <cuda_bf16.h>
#include <stdint.h>
#include <math.h>

// Problem constants (MetaS4: B=1024, H=1024, N=32)
#define BSZ 1024
#define HD  1024
#define NS  32

// ---------------------------------------------------------------------------
// Device scratch (allocation-free rule)
// ---------------------------------------------------------------------------
__device__ __align__(256) __nv_bfloat16 g_Ahi[BSZ * HD];       // y hi  [M,K]
__device__ __align__(256) __nv_bfloat16 g_Alo[BSZ * HD];       // y lo
__device__ __align__(256) __nv_bfloat16 g_Bhi[2 * HD * HD];    // W hi  [2H,K]
__device__ __align__(256) __nv_bfloat16 g_Blo[2 * HD * HD];    // W lo
__device__ __align__(256) float g_z[BSZ * 2 * HD];             // z [B,2H]

// ---------------------------------------------------------------------------
// PTX helpers (baseline ISA only — no tcgen05 on this build's ptx target)
// ---------------------------------------------------------------------------
__device__ __forceinline__ uint32_t smem_to_u32(const void* p) {
    uint32_t a;
    asm("{ .reg .u64 t; cvta.to.shared.u64 t, %1; cvt.u32.u64 %0, t; }"
        : "=r"(a) : "l"(p));
    return a;
}
__device__ __forceinline__ void cp_async16(uint32_t smem_addr, const void* gptr) {
    asm volatile("cp.async.cg.shared.global [%0], [%1], 16;\n"
                 :: "r"(smem_addr), "l"(gptr) : "memory");
}
__device__ __forceinline__ void cp_async_commit() {
    asm volatile("cp.async.commit_group;\n" ::: "memory");
}
__device__ __forceinline__ void cp_async_wait1() {
    asm volatile("cp.async.wait_group 1;\n" ::: "memory");
}
__device__ __forceinline__ void cp_async_wait0() {
    asm volatile("cp.async.wait_group 0;\n" ::: "memory");
}

#define LDMATRIX_X4(r0, r1, r2, r3, addr) \
    asm volatile("ldmatrix.sync.aligned.m8n8.x4.shared.b16 {%0,%1,%2,%3}, [%4];" \
        : "=r"(r0), "=r"(r1), "=r"(r2), "=r"(r3) : "r"(addr))

#define MMA_16816(acc, a, b0, b1) \
    asm volatile("mma.sync.aligned.m16n8k16.row.col.f32.bf16.bf16.f32 " \
        "{%0,%1,%2,%3}, {%4,%5,%6,%7}, {%8,%9}, {%0,%1,%2,%3};" \
        : "+f"((acc)[0]), "+f"((acc)[1]), "+f"((acc)[2]), "+f"((acc)[3]) \
        : "r"((a)[0]), "r"((a)[1]), "r"((a)[2]), "r"((a)[3]), \
          "r"(b0), "r"(b1))

// Swizzled smem address for a [rows][32 bf16] tile (64 B rows, 4x16B slots).
// slot' = (slot + (row>>1)) & 3  -> conflict-free for 8-lane ldmatrix phases.
__device__ __forceinline__ uint32_t swz_addr(uint32_t tile_base, int row, int slot) {
    int s = (slot + ((row >> 1) & 3)) & 3;
    return tile_base + row * 64 + s * 16;
}

// ---------------------------------------------------------------------------
// Kernel 1: complex diag state update + readout + skip + exact GELU.
// 8 threads per (b,h); each thread handles 4 n's via float4.
// ---------------------------------------------------------------------------
__global__ __launch_bounds__(256) void s4_update_kernel(
    const float* __restrict__ u,
    const float* __restrict__ st_re, const float* __restrict__ st_im,
    const float* __restrict__ dA_re, const float* __restrict__ dA_im,
    const float* __restrict__ dB_re, const float* __restrict__ dB_im,
    const float* __restrict__ C_re,  const float* __restrict__ C_im,
    const float* __restrict__ D,
    float* __restrict__ ns_re, float* __restrict__ ns_im)
{
    int t = blockIdx.x * 256 + threadIdx.x;
    int g = t >> 3;            // (b,h) flat id
    int q = t & 7;             // 4-n group index
    int h = g & (HD - 1);

    long base = (long)g * NS + q * 4;
    int  ph   = h * NS + q * 4;

    float4 sre = *(const float4*)(st_re + base);
    float4 sim = *(const float4*)(st_im + base);
    float4 are = *(const float4*)(dA_re + ph);
    float4 aim = *(const float4*)(dA_im + ph);
    float4 bre = *(const float4*)(dB_re + ph);
    float4 bim = *(const float4*)(dB_im + ph);
    float4 cre = *(const float4*)(C_re  + ph);
    float4 cim = *(const float4*)(C_im  + ph);
    float  uu  = u[g];

    float4 nre, nim;
    nre.x = fmaf(are.x, sre.x, fmaf(-aim.x, sim.x, bre.x * uu));
    nre.y = fmaf(are.y, sre.y, fmaf(-aim.y, sim.y, bre.y * uu));
    nre.z = fmaf(are.z, sre.z, fmaf(-aim.z, sim.z, bre.z * uu));
    nre.w = fmaf(are.w, sre.w, fmaf(-aim.w, sim.w, bre.w * uu));
    nim.x = fmaf(are.x, sim.x, fmaf( aim.x, sre.x, bim.x * uu));
    nim.y = fmaf(are.y, sim.y, fmaf( aim.y, sre.y, bim.y * uu));
    nim.z = fmaf(are.z, sim.z, fmaf( aim.z, sre.z, bim.z * uu));
    nim.w = fmaf(are.w, sim.w, fmaf( aim.w, sre.w, bim.w * uu));

    *(float4*)(ns_re + base) = nre;
    *(float4*)(ns_im + base) = nim;

    float p = fmaf(cre.x, nre.x, -cim.x * nim.x)
            + fmaf(cre.y, nre.y, -cim.y * nim.y)
            + fmaf(cre.z, nre.z, -cim.z * nim.z)
            + fmaf(cre.w, nre.w, -cim.w * nim.w);
    p += __shfl_xor_sync(0xFFFFFFFFu, p, 4);
    p += __shfl_xor_sync(0xFFFFFFFFu, p, 2);
    p += __shfl_xor_sync(0xFFFFFFFFu, p, 1);

    if (q == 0) {
        float y = 2.0f * p + uu * D[h];
        float gel = 0.5f * y * (1.0f + erff(y * 0.7071067811865476f));
        __nv_bfloat16 hi = __float2bfloat16(gel);
        __nv_bfloat16 lo = __float2bfloat16(gel - __bfloat162float(hi));
        g_Ahi[g] = hi;
        g_Alo[g] = lo;
    }
}

// ---------------------------------------------------------------------------
// Kernel 2: convert W (fp32) -> bf16 hi/lo split
// ---------------------------------------------------------------------------
__global__ __launch_bounds__(256) void convertW_kernel(const float* __restrict__ W)
{
    int i  = blockIdx.x * 256 + threadIdx.x;
    int i4 = i * 4;
    float4 w = *(const float4*)(W + i4);

    __nv_bfloat16 h0 = __float2bfloat16(w.x);
    __nv_bfloat16 h1 = __float2bfloat16(w.y);
    __nv_bfloat16 h2 = __float2bfloat16(w.z);
    __nv_bfloat16 h3 = __float2bfloat16(w.w);
    __nv_bfloat16 l0 = __float2bfloat16(w.x - __bfloat162float(h0));
    __nv_bfloat16 l1 = __float2bfloat16(w.y - __bfloat162float(h1));
    __nv_bfloat16 l2 = __float2bfloat16(w.z - __bfloat162float(h2));
    __nv_bfloat16 l3 = __float2bfloat16(w.w - __bfloat162float(h3));

    uint32_t hp0 = ((uint32_t)__bfloat16_as_ushort(h1) << 16) | __bfloat16_as_ushort(h0);
    uint32_t hp1 = ((uint32_t)__bfloat16_as_ushort(h3) << 16) | __bfloat16_as_ushort(h2);
    uint32_t lp0 = ((uint32_t)__bfloat16_as_ushort(l1) << 16) | __bfloat16_as_ushort(l0);
    uint32_t lp1 = ((uint32_t)__bfloat16_as_ushort(l3) << 16) | __bfloat16_as_ushort(l2);
    *(uint2*)(g_Bhi + i4) = make_uint2(hp0, hp1);
    *(uint2*)(g_Blo + i4) = make_uint2(lp0, lp1);
}

// ---------------------------------------------------------------------------
// Kernel 3: bf16-split GEMM via mma.sync.m16n8k16 (HMMA tensor path).
// Z[M=1024, N2=2048] = Y[M,K=1024] @ W[N2,K]^T + bias
// CTA 128x128, 8 warps (2 M x 4 N), warp tile 64x32, K-chunk 32, 2 stages.
// acc += Ahi*Bhi + Ahi*Blo + Alo*Bhi   (lo*lo dropped; ~2^-17 accuracy)
// NOTE: W is [N][K] row-major (K-contiguous) exactly like A, so the B
// fragment comes from NON-trans ldmatrix (row.col mma, both K-major).
// ---------------------------------------------------------------------------
#define GT       256
#define TILE_M   128
#define TILE_N   128
#define KC       32
#define NKC      (HD / KC)            // 32
#define TILE_B   (128 * KC * 2)       // 8192 bytes per bf16 tile
#define STAGE_B  (4 * TILE_B)         // 32768
#define GEMM_SMEM (2 * STAGE_B)       // 65536

__device__ __forceinline__ void load_stage(
    uint32_t st, int m0, int n0, int kc, int t)
{
    // 4 tiles x 512 16B-segments = 2048; 256 threads -> 8 each
    #pragma unroll
    for (int i = 0; i < 8; i++) {
        int idx  = i * GT + t;
        int tile = idx >> 9;          // 0..3: Ahi, Alo, Bhi, Blo
        int seg  = idx & 511;
        int row  = seg >> 2;
        int slot = seg & 3;
        const __nv_bfloat16* gb =
            (tile == 0) ? g_Ahi : (tile == 1) ? g_Alo :
            (tile == 2) ? g_Bhi : g_Blo;
        int row0 = (tile < 2) ? m0 : n0;
        const char* g = (const char*)(gb + (size_t)(row0 + row) * HD + kc * KC)
                        + slot * 16;
        cp_async16(swz_addr(st + tile * TILE_B, row, slot), g);
    }
}

__global__ __launch_bounds__(GT, 1) void gemm_tc_kernel(
    const float* __restrict__ bias, float* __restrict__ Z)
{
    extern __shared__ char smem[];
    uint32_t sb = smem_to_u32(smem);
    int t    = threadIdx.x;
    int wid  = t >> 5;
    int lane = t & 31;
    int wm   = wid & 1;              // M half (0/1)
    int wn   = wid >> 1;             // N quarter (0..3)

    int n0 = blockIdx.x * TILE_N;
    int m0 = blockIdx.y * TILE_M;

    float acc[4][4][4];
    #pragma unroll
    for (int mi = 0; mi < 4; mi++)
        #pragma unroll
        for (int ni = 0; ni < 4; ni++)
            #pragma unroll
            for (int r = 0; r < 4; r++)
                acc[mi][ni][r] = 0.0f;

    // Prologue
    load_stage(sb, m0, n0, 0, t);
    cp_async_commit();

    int lrow  = lane & 15;
    int lslot = lane >> 4;

    for (int kc = 0; kc < NKC; kc++) {
        uint32_t stage = sb + (kc & 1) * STAGE_B;

        if (kc + 1 < NKC) {
            load_stage(sb + ((kc + 1) & 1) * STAGE_B, m0, n0, kc + 1, t);
            cp_async_commit();
            cp_async_wait1();
        } else {
            cp_async_wait0();
        }
        __syncthreads();

        uint32_t stAhi = stage + 0 * TILE_B;
        uint32_t stAlo = stage + 1 * TILE_B;
        uint32_t stBhi = stage + 2 * TILE_B;
        uint32_t stBlo = stage + 3 * TILE_B;

        #pragma unroll
        for (int kk = 0; kk < 2; kk++) {
            uint32_t a_hi[4][4], a_lo[4][4], b_hi[4][2], b_lo[4][2];

            #pragma unroll
            for (int mi = 0; mi < 4; mi++) {
                int row = wm * 64 + mi * 16 + lrow;
                int slt = 2 * kk + lslot;
                LDMATRIX_X4(a_hi[mi][0], a_hi[mi][1], a_hi[mi][2], a_hi[mi][3],
                            swz_addr(stAhi, row, slt));
                LDMATRIX_X4(a_lo[mi][0], a_lo[mi][1], a_lo[mi][2], a_lo[mi][3],
                            swz_addr(stAlo, row, slt));
            }
            #pragma unroll
            for (int p = 0; p < 2; p++) {
                int row = wn * 32 + p * 16 + lrow;
                int slt = 2 * kk + lslot;
                uint32_t q0, q1, q2, q3;
                LDMATRIX_X4(q0, q1, q2, q3, swz_addr(stBhi, row, slt));
                b_hi[2 * p][0] = q0; b_hi[2 * p][1] = q2;
                b_hi[2 * p + 1][0] = q1; b_hi[2 * p + 1][1] = q3;
                LDMATRIX_X4(q0, q1, q2, q3, swz_addr(stBlo, row, slt));
                b_lo[2 * p][0] = q0; b_lo[2 * p][1] = q2;
                b_lo[2 * p + 1][0] = q1; b_lo[2 * p + 1][1] = q3;
            }

            #pragma unroll
            for (int mi = 0; mi < 4; mi++)
                #pragma unroll
                for (int ni = 0; ni < 4; ni++) {
                    MMA_16816(acc[mi][ni], a_hi[mi], b_hi[ni][0], b_hi[ni][1]);
                    MMA_16816(acc[mi][ni], a_hi[mi], b_lo[ni][0], b_lo[ni][1]);
                    MMA_16816(acc[mi][ni], a_lo[mi], b_hi[ni][0], b_hi[ni][1]);
                }
        }
        __syncthreads();
    }

    // Epilogue: bias + store
    int tr = lane >> 2;               // 0..7
    int tc = (lane & 3) * 2;
    int r_base = m0 + wm * 64;
    int c_base = n0 + wn * 32;
    #pragma unroll
    for (int mi = 0; mi < 4; mi++) {
        #pragma unroll
        for (int ni = 0; ni < 4; ni++) {
            int r = r_base + mi * 16 + tr;
            int c = c_base + ni * 8 + tc;
            float b0 = bias[c], b1 = bias[c + 1];
            float2 v0 = make_float2(acc[mi][ni][0] + b0, acc[mi][ni][1] + b1);
            float2 v1 = make_float2(acc[mi][ni][2] + b0, acc[mi][ni][3] + b1);
            *(float2*)&Z[(size_t)r * (2 * HD) + c] = v0;
            *(float2*)&Z[(size_t)(r + 8) * (2 * HD) + c] = v1;
        }
    }
}

// ---------------------------------------------------------------------------
// Kernel 4: GLU  y_out[b,j] = z[b,j] * sigmoid(z[b,H+j])   (float4)
// ---------------------------------------------------------------------------
__global__ __launch_bounds__(256) void glu_kernel(
    const float* __restrict__ Z, float* __restrict__ out)
{
    int i = (blockIdx.x * 256 + threadIdx.x) * 4;   // 0 .. B*H-1 step 4
    int b = i >> 10;
    int j = i & (HD - 1);
    float4 z1 = *(const float4*)(Z + (size_t)b * (2 * HD) + j);
    float4 z2 = *(const float4*)(Z + (size_t)b * (2 * HD) + HD + j);
    float4 v;
    v.x = z1.x * (1.0f / (1.0f + __expf(-z2.x)));
    v.y = z1.y * (1.0f / (1.0f + __expf(-z2.y)));
    v.z = z1.z * (1.0f / (1.0f + __expf(-z2.z)));
    v.w = z1.w * (1.0f / (1.0f + __expf(-z2.w)));
    *(float4*)(out + i) = v;
}

// ---------------------------------------------------------------------------
// launch
// ---------------------------------------------------------------------------
extern "C" void kernel_launch(void* const* d_in, const int* in_sizes, int n_in,
                              void* d_out, int out_size)
{
    const float* u     = (const float*)d_in[0];
    const float* st_re = (const float*)d_in[1];
    const float* st_im = (const float*)d_in[2];
    const float* dA_re = (const float*)d_in[3];
    const float* dA_im = (const float*)d_in[4];
    const float* dB_re = (const float*)d_in[5];
    const float* dB_im = (const float*)d_in[6];
    const float* C_re  = (const float*)d_in[7];
    const float* C_im  = (const float*)d_in[8];
    const float* D     = (const float*)d_in[9];
    const float* W     = (const float*)d_in[10];
    const float* bias  = (const float*)d_in[11];

    float* out   = (float*)d_out;
    float* y_out = out;                                    // [B, H]
    float* ns_re = out + (size_t)BSZ * HD;                 // [B, H, N]
    float* ns_im = out + (size_t)BSZ * HD + (size_t)BSZ * HD * NS;

    float* zbuf;  cudaGetSymbolAddress((void**)&zbuf, g_z);

    // 1) W -> bf16 hi/lo
    convertW_kernel<<<2 * HD * HD / 1024, 256>>>(W);

    // 2) state update + readout + GELU + y->bf16 split
    s4_update_kernel<<<BSZ * HD * 8 / 256, 256>>>(
        u, st_re, st_im, dA_re, dA_im, dB_re, dB_im, C_re, C_im, D,
        ns_re, ns_im);

    // 3) tensor-core (HMMA) GEMM  Z = Y @ W^T + b
    static bool attr_set = false;
    if (!attr_set) {
        cudaFuncSetAttribute(gemm_tc_kernel,
                             cudaFuncAttributeMaxDynamicSharedMemorySize,
                             GEMM_SMEM);
        attr_set = true;
    }
    {
        dim3 grid(2 * HD / TILE_N, BSZ / TILE_M);   // (16, 8)
        gemm_tc_kernel<<<grid, GT, GEMM_SMEM>>>(bias, zbuf);
    }

    // 4) GLU
    glu_kernel<<<BSZ * HD / 1024, 256>>>(zbuf, y_out);

    (void)in_sizes; (void)n_in; (void)out_size;
}

// round 6
// speedup vs baseline: 2.2029x; 1.0100x over previous
#include <cuda_runtime.h>
#include <cuda_bf16.h>
#include <stdint.h>
#include <math.h>

// Problem constants (MetaS4: B=1024, H=1024, N=32)
#define BSZ 1024
#define HD  1024
#define NS  32

// ---------------------------------------------------------------------------
// Device scratch (allocation-free rule)
// g_Bhi/g_Blo hold W in GLU-PERMUTED row order: row 2j = W[j], row 2j+1 = W[H+j]
// ---------------------------------------------------------------------------
__device__ __align__(256) __nv_bfloat16 g_Ahi[BSZ * HD];       // y hi  [M,K]
__device__ __align__(256) __nv_bfloat16 g_Alo[BSZ * HD];       // y lo
__device__ __align__(256) __nv_bfloat16 g_Bhi[2 * HD * HD];    // Wperm hi [2H,K]
__device__ __align__(256) __nv_bfloat16 g_Blo[2 * HD * HD];    // Wperm lo

// ---------------------------------------------------------------------------
// PTX helpers (baseline ISA only — no tcgen05 on this build's ptx target)
// ---------------------------------------------------------------------------
__device__ __forceinline__ uint32_t smem_to_u32(const void* p) {
    uint32_t a;
    asm("{ .reg .u64 t; cvta.to.shared.u64 t, %1; cvt.u32.u64 %0, t; }"
        : "=r"(a) : "l"(p));
    return a;
}
__device__ __forceinline__ void cp_async16(uint32_t smem_addr, const void* gptr) {
    asm volatile("cp.async.cg.shared.global [%0], [%1], 16;\n"
                 :: "r"(smem_addr), "l"(gptr) : "memory");
}
__device__ __forceinline__ void cp_async_commit() {
    asm volatile("cp.async.commit_group;\n" ::: "memory");
}
__device__ __forceinline__ void cp_async_wait1() {
    asm volatile("cp.async.wait_group 1;\n" ::: "memory");
}
__device__ __forceinline__ void cp_async_wait0() {
    asm volatile("cp.async.wait_group 0;\n" ::: "memory");
}

#define LDMATRIX_X4(r0, r1, r2, r3, addr) \
    asm volatile("ldmatrix.sync.aligned.m8n8.x4.shared.b16 {%0,%1,%2,%3}, [%4];" \
        : "=r"(r0), "=r"(r1), "=r"(r2), "=r"(r3) : "r"(addr))

#define MMA_16816(acc, a, b0, b1) \
    asm volatile("mma.sync.aligned.m16n8k16.row.col.f32.bf16.bf16.f32 " \
        "{%0,%1,%2,%3}, {%4,%5,%6,%7}, {%8,%9}, {%0,%1,%2,%3};" \
        : "+f"((acc)[0]), "+f"((acc)[1]), "+f"((acc)[2]), "+f"((acc)[3]) \
        : "r"((a)[0]), "r"((a)[1]), "r"((a)[2]), "r"((a)[3]), \
          "r"(b0), "r"(b1))

// Swizzled smem address for a [rows][32 bf16] tile (64 B rows, 4x16B slots).
__device__ __forceinline__ uint32_t swz_addr(uint32_t tile_base, int row, int slot) {
    int s = (slot + ((row >> 1) & 3)) & 3;
    return tile_base + row * 64 + s * 16;
}

// ---------------------------------------------------------------------------
// Kernel 1: complex diag state update + readout + skip + exact GELU.
// 8 threads per (b,h); each thread handles 4 n's via float4.
// Streaming hints: state/ns are touch-once (keep L2 for the [H,N] params).
// ---------------------------------------------------------------------------
__global__ __launch_bounds__(256) void s4_update_kernel(
    const float* __restrict__ u,
    const float* __restrict__ st_re, const float* __restrict__ st_im,
    const float* __restrict__ dA_re, const float* __restrict__ dA_im,
    const float* __restrict__ dB_re, const float* __restrict__ dB_im,
    const float* __restrict__ C_re,  const float* __restrict__ C_im,
    const float* __restrict__ D,
    float* __restrict__ ns_re, float* __restrict__ ns_im)
{
    int t = blockIdx.x * 256 + threadIdx.x;
    int g = t >> 3;            // (b,h) flat id
    int q = t & 7;             // 4-n group index
    int h = g & (HD - 1);

    long base = (long)g * NS + q * 4;
    int  ph   = h * NS + q * 4;

    float4 sre = __ldcs((const float4*)(st_re + base));
    float4 sim = __ldcs((const float4*)(st_im + base));
    float4 are = *(const float4*)(dA_re + ph);
    float4 aim = *(const float4*)(dA_im + ph);
    float4 bre = *(const float4*)(dB_re + ph);
    float4 bim = *(const float4*)(dB_im + ph);
    float4 cre = *(const float4*)(C_re  + ph);
    float4 cim = *(const float4*)(C_im  + ph);
    float  uu  = u[g];

    float4 nre, nim;
    nre.x = fmaf(are.x, sre.x, fmaf(-aim.x, sim.x, bre.x * uu));
    nre.y = fmaf(are.y, sre.y, fmaf(-aim.y, sim.y, bre.y * uu));
    nre.z = fmaf(are.z, sre.z, fmaf(-aim.z, sim.z, bre.z * uu));
    nre.w = fmaf(are.w, sre.w, fmaf(-aim.w, sim.w, bre.w * uu));
    nim.x = fmaf(are.x, sim.x, fmaf( aim.x, sre.x, bim.x * uu));
    nim.y = fmaf(are.y, sim.y, fmaf( aim.y, sre.y, bim.y * uu));
    nim.z = fmaf(are.z, sim.z, fmaf( aim.z, sre.z, bim.z * uu));
    nim.w = fmaf(are.w, sim.w, fmaf( aim.w, sre.w, bim.w * uu));

    __stcs((float4*)(ns_re + base), nre);
    __stcs((float4*)(ns_im + base), nim);

    float p = fmaf(cre.x, nre.x, -cim.x * nim.x)
            + fmaf(cre.y, nre.y, -cim.y * nim.y)
            + fmaf(cre.z, nre.z, -cim.z * nim.z)
            + fmaf(cre.w, nre.w, -cim.w * nim.w);
    p += __shfl_xor_sync(0xFFFFFFFFu, p, 4);
    p += __shfl_xor_sync(0xFFFFFFFFu, p, 2);
    p += __shfl_xor_sync(0xFFFFFFFFu, p, 1);

    if (q == 0) {
        float y = 2.0f * p + uu * D[h];
        float gel = 0.5f * y * (1.0f + erff(y * 0.7071067811865476f));
        __nv_bfloat16 hi = __float2bfloat16(gel);
        __nv_bfloat16 lo = __float2bfloat16(gel - __bfloat162float(hi));
        g_Ahi[g] = hi;
        g_Alo[g] = lo;
    }
}

// ---------------------------------------------------------------------------
// Kernel 2: convert W (fp32) -> bf16 hi/lo split, GLU-permuted rows:
//   orig row i < H   -> dest row 2i      (z1 operand)
//   orig row i >= H  -> dest row 2(i-H)+1 (z2 / gate operand)
// ---------------------------------------------------------------------------
__global__ __launch_bounds__(256) void convertW_kernel(const float* __restrict__ W)
{
    int i  = blockIdx.x * 256 + threadIdx.x;
    int i4 = i * 4;
    int row = i4 >> 10;          // / HD
    int col = i4 & (HD - 1);
    int drow = (row < HD) ? (2 * row) : (2 * (row - HD) + 1);
    size_t dst = (size_t)drow * HD + col;

    float4 w = *(const float4*)(W + i4);

    __nv_bfloat16 h0 = __float2bfloat16(w.x);
    __nv_bfloat16 h1 = __float2bfloat16(w.y);
    __nv_bfloat16 h2 = __float2bfloat16(w.z);
    __nv_bfloat16 h3 = __float2bfloat16(w.w);
    __nv_bfloat16 l0 = __float2bfloat16(w.x - __bfloat162float(h0));
    __nv_bfloat16 l1 = __float2bfloat16(w.y - __bfloat162float(h1));
    __nv_bfloat16 l2 = __float2bfloat16(w.z - __bfloat162float(h2));
    __nv_bfloat16 l3 = __float2bfloat16(w.w - __bfloat162float(h3));

    uint32_t hp0 = ((uint32_t)__bfloat16_as_ushort(h1) << 16) | __bfloat16_as_ushort(h0);
    uint32_t hp1 = ((uint32_t)__bfloat16_as_ushort(h3) << 16) | __bfloat16_as_ushort(h2);
    uint32_t lp0 = ((uint32_t)__bfloat16_as_ushort(l1) << 16) | __bfloat16_as_ushort(l0);
    uint32_t lp1 = ((uint32_t)__bfloat16_as_ushort(l3) << 16) | __bfloat16_as_ushort(l2);
    *(uint2*)(g_Bhi + dst) = make_uint2(hp0, hp1);
    *(uint2*)(g_Blo + dst) = make_uint2(lp0, lp1);
}

// ---------------------------------------------------------------------------
// Kernel 3: bf16-split GEMM via mma.sync.m16n8k16 + fused GLU epilogue.
// Zperm[M, 2H] = Y @ Wperm^T + bperm; out[m, j] = z1 * sigmoid(z2) where
// permuted cols (2j, 2j+1) = (z1[j], z2[j]) sit in one accumulator pair.
// CTA 128x128(permuted cols) = 64 output cols. 8 warps, K-chunk 32, 2 stages.
// ---------------------------------------------------------------------------
#define GT       256
#define TILE_M   128
#define TILE_N   128
#define KC       32
#define NKC      (HD / KC)            // 32
#define TILE_B   (128 * KC * 2)       // 8192 bytes per bf16 tile
#define STAGE_B  (4 * TILE_B)         // 32768
#define GEMM_SMEM (2 * STAGE_B)       // 65536

__device__ __forceinline__ void load_stage(
    uint32_t st, int m0, int n0, int kc, int t)
{
    #pragma unroll
    for (int i = 0; i < 8; i++) {
        int idx  = i * GT + t;
        int tile = idx >> 9;          // 0..3: Ahi, Alo, Bhi, Blo
        int seg  = idx & 511;
        int row  = seg >> 2;
        int slot = seg & 3;
        const __nv_bfloat16* gb =
            (tile == 0) ? g_Ahi : (tile == 1) ? g_Alo :
            (tile == 2) ? g_Bhi : g_Blo;
        int row0 = (tile < 2) ? m0 : n0;
        const char* g = (const char*)(gb + (size_t)(row0 + row) * HD + kc * KC)
                        + slot * 16;
        cp_async16(swz_addr(st + tile * TILE_B, row, slot), g);
    }
}

__global__ __launch_bounds__(GT, 1) void gemm_tc_kernel(
    const float* __restrict__ bias, float* __restrict__ out)
{
    extern __shared__ char smem[];
    uint32_t sb = smem_to_u32(smem);
    int t    = threadIdx.x;
    int wid  = t >> 5;
    int lane = t & 31;
    int wm   = wid & 1;              // M half (0/1)
    int wn   = wid >> 1;             // N quarter (0..3)

    int n0 = blockIdx.x * TILE_N;    // permuted-W row range
    int m0 = blockIdx.y * TILE_M;

    float acc[4][4][4];
    #pragma unroll
    for (int mi = 0; mi < 4; mi++)
        #pragma unroll
        for (int ni = 0; ni < 4; ni++)
            #pragma unroll
            for (int r = 0; r < 4; r++)
                acc[mi][ni][r] = 0.0f;

    // Prologue
    load_stage(sb, m0, n0, 0, t);
    cp_async_commit();

    int lrow  = lane & 15;
    int lslot = lane >> 4;

    for (int kc = 0; kc < NKC; kc++) {
        uint32_t stage = sb + (kc & 1) * STAGE_B;

        if (kc + 1 < NKC) {
            load_stage(sb + ((kc + 1) & 1) * STAGE_B, m0, n0, kc + 1, t);
            cp_async_commit();
            cp_async_wait1();
        } else {
            cp_async_wait0();
        }
        __syncthreads();

        uint32_t stAhi = stage + 0 * TILE_B;
        uint32_t stAlo = stage + 1 * TILE_B;
        uint32_t stBhi = stage + 2 * TILE_B;
        uint32_t stBlo = stage + 3 * TILE_B;

        #pragma unroll
        for (int kk = 0; kk < 2; kk++) {
            uint32_t a_hi[4][4], a_lo[4][4], b_hi[4][2], b_lo[4][2];

            #pragma unroll
            for (int mi = 0; mi < 4; mi++) {
                int row = wm * 64 + mi * 16 + lrow;
                int slt = 2 * kk + lslot;
                LDMATRIX_X4(a_hi[mi][0], a_hi[mi][1], a_hi[mi][2], a_hi[mi][3],
                            swz_addr(stAhi, row, slt));
                LDMATRIX_X4(a_lo[mi][0], a_lo[mi][1], a_lo[mi][2], a_lo[mi][3],
                            swz_addr(stAlo, row, slt));
            }
            #pragma unroll
            for (int p = 0; p < 2; p++) {
                int row = wn * 32 + p * 16 + lrow;
                int slt = 2 * kk + lslot;
                uint32_t q0, q1, q2, q3;
                LDMATRIX_X4(q0, q1, q2, q3, swz_addr(stBhi, row, slt));
                b_hi[2 * p][0] = q0; b_hi[2 * p][1] = q2;
                b_hi[2 * p + 1][0] = q1; b_hi[2 * p + 1][1] = q3;
                LDMATRIX_X4(q0, q1, q2, q3, swz_addr(stBlo, row, slt));
                b_lo[2 * p][0] = q0; b_lo[2 * p][1] = q2;
                b_lo[2 * p + 1][0] = q1; b_lo[2 * p + 1][1] = q3;
            }

            #pragma unroll
            for (int mi = 0; mi < 4; mi++)
                #pragma unroll
                for (int ni = 0; ni < 4; ni++) {
                    MMA_16816(acc[mi][ni], a_hi[mi], b_hi[ni][0], b_hi[ni][1]);
                    MMA_16816(acc[mi][ni], a_hi[mi], b_lo[ni][0], b_lo[ni][1]);
                    MMA_16816(acc[mi][ni], a_lo[mi], b_hi[ni][0], b_hi[ni][1]);
                }
        }
        __syncthreads();
    }

    // Fused GLU epilogue.
    // Thread fragment cols (c, c+1) with c even = permuted (2j, 2j+1)
    //   -> out col j = c >> 1; b0 = bias[j], b1 = bias[H + j].
    int tr = lane >> 2;               // 0..7
    int tc = (lane & 3) * 2;
    int r_base = m0 + wm * 64;
    int c_base = n0 + wn * 32;
    #pragma unroll
    for (int mi = 0; mi < 4; mi++) {
        #pragma unroll
        for (int ni = 0; ni < 4; ni++) {
            int r = r_base + mi * 16 + tr;
            int j = (c_base + ni * 8 + tc) >> 1;
            float b0 = bias[j], b1 = bias[HD + j];
            float z1a = acc[mi][ni][0] + b0;
            float z2a = acc[mi][ni][1] + b1;
            float z1b = acc[mi][ni][2] + b0;
            float z2b = acc[mi][ni][3] + b1;
            out[(size_t)r * HD + j]       = z1a * (1.0f / (1.0f + __expf(-z2a)));
            out[(size_t)(r + 8) * HD + j] = z1b * (1.0f / (1.0f + __expf(-z2b)));
        }
    }
}

// ---------------------------------------------------------------------------
// launch
// ---------------------------------------------------------------------------
extern "C" void kernel_launch(void* const* d_in, const int* in_sizes, int n_in,
                              void* d_out, int out_size)
{
    const float* u     = (const float*)d_in[0];
    const float* st_re = (const float*)d_in[1];
    const float* st_im = (const float*)d_in[2];
    const float* dA_re = (const float*)d_in[3];
    const float* dA_im = (const float*)d_in[4];
    const float* dB_re = (const float*)d_in[5];
    const float* dB_im = (const float*)d_in[6];
    const float* C_re  = (const float*)d_in[7];
    const float* C_im  = (const float*)d_in[8];
    const float* D     = (const float*)d_in[9];
    const float* W     = (const float*)d_in[10];
    const float* bias  = (const float*)d_in[11];

    float* out   = (float*)d_out;
    float* y_out = out;                                    // [B, H]
    float* ns_re = out + (size_t)BSZ * HD;                 // [B, H, N]
    float* ns_im = out + (size_t)BSZ * HD + (size_t)BSZ * HD * NS;

    // 1) W -> bf16 hi/lo (GLU-permuted rows)
    convertW_kernel<<<2 * HD * HD / 1024, 256>>>(W);

    // 2) state update + readout + GELU + y->bf16 split
    s4_update_kernel<<<BSZ * HD * 8 / 256, 256>>>(
        u, st_re, st_im, dA_re, dA_im, dB_re, dB_im, C_re, C_im, D,
        ns_re, ns_im);

    // 3) tensor-core (HMMA) GEMM + fused GLU -> y_out
    static bool attr_set = false;
    if (!attr_set) {
        cudaFuncSetAttribute(gemm_tc_kernel,
                             cudaFuncAttributeMaxDynamicSharedMemorySize,
                             GEMM_SMEM);
        attr_set = true;
    }
    {
        dim3 grid(2 * HD / TILE_N, BSZ / TILE_M);   // (16, 8)
        gemm_tc_kernel<<<grid, GT, GEMM_SMEM>>>(bias, y_out);
    }

    (void)in_sizes; (void)n_in; (void)out_size;
}